// round 4
// baseline (speedup 1.0000x reference)
#include <cuda_runtime.h>
#include <cstdint>

// Per-token int4 quantization (persistent-CTA streaming version):
//   x: [N, H] fp32 (H = 4096)
//   scales[n] = max|x[n,:]| / 7
//   q = rint(x * 7/max)        (in [-7,7] by construction; clamp-free)
//   packed byte = ((q_odd & 0xF) << 4) | (q_even & 0xF)  (as signed int8 value)
//
// Harness output layout (detected via out_size):
//   FLOAT_OUT: [N*H/2 float32 (packed byte values)][N float32 scales]
//   BYTE_OUT : [N*H/2 int8][N float32 scales]

constexpr int H       = 4096;
constexpr int THREADS = 256;
constexpr int CHUNKS  = H / 4 / THREADS;  // 4 float4-chunks per thread
constexpr int GRID    = 152 * 8;          // persistent: one wave on GB300 (152 SMs)

template <bool FLOAT_OUT>
__global__ __launch_bounds__(THREADS, 8)
void quant_int4_kernel(const float* __restrict__ x,
                       void* __restrict__ packed_out,
                       float* __restrict__ scales,
                       int rows)
{
    const int t = threadIdx.x;
    __shared__ float smax[2][THREADS / 32];  // double-buffered: no WAR barrier

    int buf = 0;
    for (int row = blockIdx.x; row < rows; row += gridDim.x, buf ^= 1) {
        const float4* xr = reinterpret_cast<const float4*>(x + (size_t)row * H);

        // Coalesced streaming loads: lane-consecutive float4 per LDG.128.
        float4 v[CHUNKS];
#pragma unroll
        for (int k = 0; k < CHUNKS; ++k)
            v[k] = __ldcs(&xr[t + THREADS * k]);

        // Local max|x|
        float m = 0.0f;
#pragma unroll
        for (int k = 0; k < CHUNKS; ++k) {
            m = fmaxf(m, fmaxf(fmaxf(fabsf(v[k].x), fabsf(v[k].y)),
                               fmaxf(fabsf(v[k].z), fabsf(v[k].w))));
        }

        // Warp reduce
#pragma unroll
        for (int o = 16; o > 0; o >>= 1)
            m = fmaxf(m, __shfl_xor_sync(0xffffffffu, m, o));

        if ((t & 31) == 0) smax[buf][t >> 5] = m;
        __syncthreads();

        float rowmax = smax[buf][0];
#pragma unroll
        for (int w = 1; w < THREADS / 32; ++w)
            rowmax = fmaxf(rowmax, smax[buf][w]);

        const float scale = rowmax / 7.0f;                     // exact fp32
        const float inv   = (rowmax > 0.0f) ? 7.0f / rowmax : 0.0f;

        if (t == 0) scales[row] = scale;

        // Quantize each float4 chunk -> 2 packed bytes. No clamps needed:
        // |x| <= rowmax implies |x*inv| <= 7 (+1ulp), rint stays in [-7,7].
        if (FLOAT_OUT) {
            float2* op = reinterpret_cast<float2*>((float*)packed_out + (size_t)row * (H / 2));
#pragma unroll
            for (int k = 0; k < CHUNKS; ++k) {
                int q0 = __float2int_rn(v[k].x * inv);
                int q1 = __float2int_rn(v[k].y * inv);
                int q2 = __float2int_rn(v[k].z * inv);
                int q3 = __float2int_rn(v[k].w * inv);
                float b0 = (float)(int)(int8_t)(((q1 & 0xF) << 4) | (q0 & 0xF));
                float b1 = (float)(int)(int8_t)(((q3 & 0xF) << 4) | (q2 & 0xF));
                __stcs(&op[t + THREADS * k], make_float2(b0, b1));
            }
        } else {
            uint16_t* op = reinterpret_cast<uint16_t*>((int8_t*)packed_out + (size_t)row * (H / 2));
#pragma unroll
            for (int k = 0; k < CHUNKS; ++k) {
                int q0 = __float2int_rn(v[k].x * inv);
                int q1 = __float2int_rn(v[k].y * inv);
                int q2 = __float2int_rn(v[k].z * inv);
                int q3 = __float2int_rn(v[k].w * inv);
                uint16_t b = (uint16_t)((((q3 & 0xF) << 4) | (q2 & 0xF)) << 8
                                      | (((q1 & 0xF) << 4) | (q0 & 0xF)));
                op[t + THREADS * k] = b;
            }
        }
    }
}

extern "C" void kernel_launch(void* const* d_in, const int* in_sizes, int n_in,
                              void* d_out, int out_size)
{
    const float* x = (const float*)d_in[0];
    const int rows = in_sizes[0] / H;
    const long long packed_elems = (long long)rows * (H / 2);
    const int grid = rows < GRID ? rows : GRID;

    if ((long long)out_size == packed_elems + rows) {
        // float32 layout: packed values as floats, then scales
        float* packed = (float*)d_out;
        float* scales = packed + packed_elems;
        quant_int4_kernel<true><<<grid, THREADS>>>(x, packed, scales, rows);
    } else {
        // int8 layout: packed bytes, then fp32 scales appended as raw bytes
        int8_t* packed = (int8_t*)d_out;
        float*  scales = (float*)(packed + packed_elems);
        quant_int4_kernel<false><<<grid, THREADS>>>(x, packed, scales, rows);
    }
}

// round 5
// speedup vs baseline: 1.0185x; 1.0185x over previous
#include <cuda_runtime.h>
#include <cstdint>

// Per-token int4 quantization:
//   x: [N, H] fp32 (H = 4096)
//   scales[n] = max|x[n,:]| / 7
//   q = rint(x * 7/max)   (in [-7,7] by construction; clamp-free)
//   packed byte = ((q_odd & 0xF) << 4) | (q_even & 0xF)  (as signed int8 value)
//
// Harness output layout (detected via out_size):
//   FLOAT_OUT: [N*H/2 float32 (packed byte values)][N float32 scales]
//   BYTE_OUT : [N*H/2 int8][N float32 scales]
//
// One CTA per row (classic launch was fastest: perfect-balance wave schedule).
// All memory instructions lane-consecutive; streaming cache hints (zero reuse).

constexpr int H       = 4096;
constexpr int THREADS = 256;
constexpr int CHUNKS  = H / 4 / THREADS;  // 4 float4-chunks per thread

template <bool FLOAT_OUT>
__global__ __launch_bounds__(THREADS, 8)
void quant_int4_kernel(const float* __restrict__ x,
                       void* __restrict__ packed_out,
                       float* __restrict__ scales)
{
    const int row = blockIdx.x;
    const int t   = threadIdx.x;

    const float4* xr = reinterpret_cast<const float4*>(x + (size_t)row * H);

    // Coalesced streaming loads: lane-consecutive float4 per LDG.128,
    // all 4 front-batched for max MLP.
    float4 v[CHUNKS];
#pragma unroll
    for (int k = 0; k < CHUNKS; ++k)
        v[k] = __ldcs(&xr[t + THREADS * k]);

    // Local max|x|
    float m = 0.0f;
#pragma unroll
    for (int k = 0; k < CHUNKS; ++k) {
        m = fmaxf(m, fmaxf(fmaxf(fabsf(v[k].x), fabsf(v[k].y)),
                           fmaxf(fabsf(v[k].z), fabsf(v[k].w))));
    }

    // Warp reduce
#pragma unroll
    for (int o = 16; o > 0; o >>= 1)
        m = fmaxf(m, __shfl_xor_sync(0xffffffffu, m, o));

    __shared__ float smax[THREADS / 32];
    if ((t & 31) == 0) smax[t >> 5] = m;
    __syncthreads();

    float rowmax = smax[0];
#pragma unroll
    for (int w = 1; w < THREADS / 32; ++w)
        rowmax = fmaxf(rowmax, smax[w]);

    const float scale = rowmax / 7.0f;                        // exact fp32
    const float inv   = (rowmax > 0.0f) ? 7.0f / rowmax : 0.0f;

    if (t == 0) scales[row] = scale;

    // Quantize each float4 chunk -> 2 packed bytes. Clamp-free:
    // |x| <= rowmax implies |x*inv| <= 7 (+1ulp), rint stays in [-7,7].
    if (FLOAT_OUT) {
        float2* op = reinterpret_cast<float2*>((float*)packed_out + (size_t)row * (H / 2));
#pragma unroll
        for (int k = 0; k < CHUNKS; ++k) {
            int q0 = __float2int_rn(v[k].x * inv);
            int q1 = __float2int_rn(v[k].y * inv);
            int q2 = __float2int_rn(v[k].z * inv);
            int q3 = __float2int_rn(v[k].w * inv);
            float b0 = (float)(int)(int8_t)(((q1 & 0xF) << 4) | (q0 & 0xF));
            float b1 = (float)(int)(int8_t)(((q3 & 0xF) << 4) | (q2 & 0xF));
            __stcs(&op[t + THREADS * k], make_float2(b0, b1));
        }
    } else {
        uint16_t* op = reinterpret_cast<uint16_t*>((int8_t*)packed_out + (size_t)row * (H / 2));
#pragma unroll
        for (int k = 0; k < CHUNKS; ++k) {
            int q0 = __float2int_rn(v[k].x * inv);
            int q1 = __float2int_rn(v[k].y * inv);
            int q2 = __float2int_rn(v[k].z * inv);
            int q3 = __float2int_rn(v[k].w * inv);
            uint16_t b = (uint16_t)((((q3 & 0xF) << 4) | (q2 & 0xF)) << 8
                                  | (((q1 & 0xF) << 4) | (q0 & 0xF)));
            op[t + THREADS * k] = b;
        }
    }
}

extern "C" void kernel_launch(void* const* d_in, const int* in_sizes, int n_in,
                              void* d_out, int out_size)
{
    const float* x = (const float*)d_in[0];
    const int rows = in_sizes[0] / H;
    const long long packed_elems = (long long)rows * (H / 2);

    if ((long long)out_size == packed_elems + rows) {
        // float32 layout: packed values as floats, then scales
        float* packed = (float*)d_out;
        float* scales = packed + packed_elems;
        quant_int4_kernel<true><<<rows, THREADS>>>(x, packed, scales);
    } else {
        // int8 layout: packed bytes, then fp32 scales appended as raw bytes
        int8_t* packed = (int8_t*)d_out;
        float*  scales = (float*)(packed + packed_elems);
        quant_int4_kernel<false><<<rows, THREADS>>>(x, packed, scales);
    }
}

// round 6
// speedup vs baseline: 1.0234x; 1.0049x over previous
#include <cuda_runtime.h>
#include <cstdint>

// Per-token int4 quantization:
//   x: [N, H] fp32 (H = 4096)
//   scales[n] = max|x[n,:]| / 7
//   q = rint(x * 7/max)   (in [-7,7] by construction; clamp-free)
//   packed byte = ((q_odd & 0xF) << 4) | (q_even & 0xF)  (as signed int8 value)
//
// FLOAT_OUT epilogue uses the pure-float identity (exact for q in [-8,7]):
//   byte_val = 16*q1 + (q0 + 16*[q0<0])
// so no int conversions appear in the hot path.
//
// Harness output layout (detected via out_size):
//   FLOAT_OUT: [N*H/2 float32 (packed byte values)][N float32 scales]
//   BYTE_OUT : [N*H/2 int8][N float32 scales]

constexpr int H       = 4096;
constexpr int THREADS = 256;
constexpr int CHUNKS  = H / 4 / THREADS;  // 4 float4-chunks per thread

template <bool FLOAT_OUT>
__global__ __launch_bounds__(THREADS, 8)
void quant_int4_kernel(const float* __restrict__ x,
                       void* __restrict__ packed_out,
                       float* __restrict__ scales)
{
    const int row = blockIdx.x;
    const int t   = threadIdx.x;

    const float4* xr = reinterpret_cast<const float4*>(x + (size_t)row * H);

    // Coalesced streaming loads: lane-consecutive float4 per LDG.128,
    // all 4 front-batched for max MLP.
    float4 v[CHUNKS];
#pragma unroll
    for (int k = 0; k < CHUNKS; ++k)
        v[k] = __ldcs(&xr[t + THREADS * k]);

    // Local max|x|
    float m = 0.0f;
#pragma unroll
    for (int k = 0; k < CHUNKS; ++k) {
        m = fmaxf(m, fmaxf(fmaxf(fabsf(v[k].x), fabsf(v[k].y)),
                           fmaxf(fabsf(v[k].z), fabsf(v[k].w))));
    }

    // Warp reduce
#pragma unroll
    for (int o = 16; o > 0; o >>= 1)
        m = fmaxf(m, __shfl_xor_sync(0xffffffffu, m, o));

    __shared__ float smax[THREADS / 32];
    if ((t & 31) == 0) smax[t >> 5] = m;
    __syncthreads();

    float rowmax = smax[0];
#pragma unroll
    for (int w = 1; w < THREADS / 32; ++w)
        rowmax = fmaxf(rowmax, smax[w]);

    const float scale = rowmax / 7.0f;                        // exact fp32
    const float inv   = (rowmax > 0.0f) ? 7.0f / rowmax : 0.0f;

    if (t == 0) scales[row] = scale;

    if (FLOAT_OUT) {
        float2* op = reinterpret_cast<float2*>((float*)packed_out + (size_t)row * (H / 2));
#pragma unroll
        for (int k = 0; k < CHUNKS; ++k) {
            // rintf == FRND round-half-even, identical to __float2int_rn path.
            float q0 = rintf(v[k].x * inv);
            float q1 = rintf(v[k].y * inv);
            float q2 = rintf(v[k].z * inv);
            float q3 = rintf(v[k].w * inv);
            // low-nibble value: q + 16 if q < 0 (maps [-8,-1] -> [8,15])
            float n0 = q0 + (q0 < 0.0f ? 16.0f : 0.0f);
            float n2 = q2 + (q2 < 0.0f ? 16.0f : 0.0f);
            float b0 = fmaf(16.0f, q1, n0);   // exact: integers < 2^24
            float b1 = fmaf(16.0f, q3, n2);
            __stcs(&op[t + THREADS * k], make_float2(b0, b1));
        }
    } else {
        uint16_t* op = reinterpret_cast<uint16_t*>((int8_t*)packed_out + (size_t)row * (H / 2));
#pragma unroll
        for (int k = 0; k < CHUNKS; ++k) {
            int q0 = __float2int_rn(v[k].x * inv);
            int q1 = __float2int_rn(v[k].y * inv);
            int q2 = __float2int_rn(v[k].z * inv);
            int q3 = __float2int_rn(v[k].w * inv);
            uint16_t b = (uint16_t)((((q3 & 0xF) << 4) | (q2 & 0xF)) << 8
                                  | (((q1 & 0xF) << 4) | (q0 & 0xF)));
            op[t + THREADS * k] = b;
        }
    }
}

extern "C" void kernel_launch(void* const* d_in, const int* in_sizes, int n_in,
                              void* d_out, int out_size)
{
    const float* x = (const float*)d_in[0];
    const int rows = in_sizes[0] / H;
    const long long packed_elems = (long long)rows * (H / 2);

    if ((long long)out_size == packed_elems + rows) {
        // float32 layout: packed values as floats, then scales
        float* packed = (float*)d_out;
        float* scales = packed + packed_elems;
        quant_int4_kernel<true><<<rows, THREADS>>>(x, packed, scales);
    } else {
        // int8 layout: packed bytes, then fp32 scales appended as raw bytes
        int8_t* packed = (int8_t*)d_out;
        float*  scales = (float*)(packed + packed_elems);
        quant_int4_kernel<false><<<rows, THREADS>>>(x, packed, scales);
    }
}